// round 9
// baseline (speedup 1.0000x reference)
#include <cuda_runtime.h>
#include <cstdint>

// Blocked Hadamard transform, BLOCK = 256 = 4^4.
// H4 = ones(4) - 2*antidiag ; H = kron(H4 x4) / 16.  Note 3-d = d^3, so
// H4: y_d = sum(x) - 2*x_{d^3}.
//
// Warp tile = 512 consecutive floats (2 blocks). Float-address bits a0..a8:
//   local:  a0,a1 (float4 elem), a5,a7 (chunk bits -> chunk offsets 0,32,128,160)
//   lane:   a2,a3,a4 (l0..l2, forced for 128B-line coalescing), a6 (l3), a8 (l4)
// Digits: i0={a0,a1} local^2 (free)   i1={a2,a3} lane^2 (2-shuffle identity)
//         i2={a4,a5} split (lane low, local high)  i3={a6,a7} split
// Split-digit butterfly (1 shuffle per local pair (A,B), mask m = digit's lane bit):
//   s=A+B; d=A-B; ds=shfl_xor(d,m); A'=s+ds; B'=s-ds
// Total 48 shuffles/thread (vs 80 for all-lane stages). All IO is LDG.128/STG.128
// on full 128B lines.

__global__ void __launch_bounds__(256) hadamard256_kernel(
    const float* __restrict__ x, float* __restrict__ out)
{
    const unsigned warp_global = blockIdx.x * 8u + (threadIdx.x >> 5);
    const unsigned lane = threadIdx.x & 31u;
    // laneoff = 4*l0..2 + 64*l3 + 256*l4   (floats)
    const unsigned laneoff = 4u * (lane & 7u) + 64u * ((lane >> 3) & 1u)
                           + 256u * (lane >> 4);
    const size_t base = (size_t)warp_global * 512u + laneoff;

    // chunk float4 offsets: floats {0,32,128,160} -> float4 {0,8,32,40}
    const float4* xp = reinterpret_cast<const float4*>(x + base);

    float V[16];
    #pragma unroll
    for (int k = 0; k < 4; k++) {
        const int off4 = (k & 1) * 8 + (k >> 1) * 32;
        float4 t = __ldcs(xp + off4);
        // ---- Stage i0 (local H4 within the float4) ----
        float s01 = t.x + t.y, d01 = t.x - t.y;
        float s23 = t.z + t.w, d23 = t.z - t.w;
        V[4*k + 0] = s01 + d23;   //  x0+x1+x2-x3
        V[4*k + 1] = s01 - d23;   //  x0+x1-x2+x3
        V[4*k + 2] = d01 + s23;   //  x0-x1+x2+x3
        V[4*k + 3] = s23 - d01;   // -x0+x1+x2+x3
    }

    // ---- Stage i2: split digit, lane bit = l2 (mask 4), local pair = chunk bit a5.
    // Pairs (V[i], V[i+4]) for i in {0..3, 8..11}.
    #pragma unroll
    for (int h = 0; h < 2; h++) {
        #pragma unroll
        for (int e = 0; e < 4; e++) {
            const int i = 8 * h + e;
            float A = V[i], B = V[i + 4];
            float s = A + B, d = A - B;
            float ds = __shfl_xor_sync(0xffffffffu, d, 4);
            V[i]     = s + ds;
            V[i + 4] = s - ds;
        }
    }

    // ---- Stage i3: split digit, lane bit = l3 (mask 8), local pair = chunk bit a7.
    // Pairs (V[i], V[i+8]) for i in 0..7.
    #pragma unroll
    for (int i = 0; i < 8; i++) {
        float A = V[i], B = V[i + 8];
        float s = A + B, d = A - B;
        float ds = __shfl_xor_sync(0xffffffffu, d, 8);
        V[i]     = s + ds;
        V[i + 8] = s - ds;
    }

    // ---- Stage i1: lane^2 digit (bits l0,l1), 2-shuffle identity; fold 1/16 ----
    #pragma unroll
    for (int i = 0; i < 16; i++) {
        float a  = __shfl_xor_sync(0xffffffffu, V[i], 1);
        float s  = V[i] + a;
        float t  = V[i] - a;
        float t2 = __shfl_xor_sync(0xffffffffu, t, 2);
        V[i] = (s + t2) * 0.0625f;
    }

    float4* op = reinterpret_cast<float4*>(out + base);
    #pragma unroll
    for (int k = 0; k < 4; k++) {
        const int off4 = (k & 1) * 8 + (k >> 1) * 32;
        __stcs(op + off4, make_float4(V[4*k], V[4*k+1], V[4*k+2], V[4*k+3]));
    }
}

extern "C" void kernel_launch(void* const* d_in, const int* in_sizes, int n_in,
                              void* d_out, int out_size)
{
    const float* x = (const float*)d_in[0];
    float* out = (float*)d_out;

    // out_size = 2*4096*8192 = 67,108,864 floats.
    // One warp handles 512 floats; 8 warps (256 threads) per CTA -> 4096 floats/CTA.
    const long long n = (long long)out_size;
    const int cta_elems = 4096;
    const int grid = (int)(n / cta_elems);   // 16384, exact

    hadamard256_kernel<<<grid, 256>>>(x, out);
}

// round 11
// speedup vs baseline: 1.0301x; 1.0301x over previous
#include <cuda_runtime.h>
#include <cstdint>

// Blocked Hadamard transform, BLOCK = 256 = 4^4.
// H4 = ones(4) - 2*antidiag ; H = kron(H4 x4) / 16.
// In-block index i = i0 + 4*i1 + 16*i2 + 64*i3 (base-4 digits).
//
// Warp handles 512 consecutive floats (2 blocks) as 4 float4 chunks per thread:
//   idx = 4*lane + e + 128*c,  e in [0,4), c in [0,4)
//   -> i0 = e (register-local), i1 = lane[1:0], i2 = lane[3:2],
//      i3 = (c&1)<<1 | lane[4], block = c>>1.
// All global accesses are warp-contiguous LDG.128/STG.128 (512B per inst).
//
// Stage costs per thread: i0 free (in-register), i3 split-digit butterfly
// (1 shuffle per chunk pair on the difference: 8 SHFL), i1/i2 two-shuffle
// identity (32 SHFL each). 72 SHFL total (was 80 in R6).

__global__ void __launch_bounds__(256) hadamard256_kernel(
    const float* __restrict__ x, float* __restrict__ out)
{
    const unsigned warp_global = blockIdx.x * 8u + (threadIdx.x >> 5);
    const unsigned lane = threadIdx.x & 31u;
    // base in float4 units; warp accesses are contiguous 512B per instruction
    const size_t base4 = (size_t)warp_global * 128u + lane;

    const float4* xp = reinterpret_cast<const float4*>(x) + base4;

    float4 v[4];
    #pragma unroll
    for (int c = 0; c < 4; c++) {
        float4 t = __ldcs(xp + 32 * c);
        // ---- Stage i0 (register-local H4 within the float4) ----
        float s01 = t.x + t.y, d01 = t.x - t.y;
        float s23 = t.z + t.w, d23 = t.z - t.w;
        v[c].x = s01 + d23;   //  x0+x1+x2-x3
        v[c].y = s01 - d23;   //  x0+x1-x2+x3
        v[c].z = d01 + s23;   //  x0-x1+x2+x3
        v[c].w = s23 - d01;   // -x0+x1+x2+x3
    }

    // ---- Stage i3: split digit (low bit = lane bit 4, high bit = c bit 0).
    // Pairs (c=0,c=1) and (c=2,c=3); ONE shuffle per element pair:
    //   s = A+B; d = A-B; ds = shfl_xor(d,16); A' = s+ds; B' = s-ds
    #pragma unroll
    for (int p = 0; p < 2; p++) {
        float* A = reinterpret_cast<float*>(&v[2 * p]);
        float* B = reinterpret_cast<float*>(&v[2 * p + 1]);
        #pragma unroll
        for (int e = 0; e < 4; e++) {
            float s = A[e] + B[e];
            float d = A[e] - B[e];
            float ds = __shfl_xor_sync(0xffffffffu, d, 16);
            A[e] = s + ds;
            B[e] = s - ds;
        }
    }

    // ---- Stage i1: lane bits [1:0], 2-shuffle identity ----
    {
        float* f = reinterpret_cast<float*>(v);
        #pragma unroll
        for (int j = 0; j < 16; j++) {
            float a  = __shfl_xor_sync(0xffffffffu, f[j], 1);
            float s  = f[j] + a;
            float d  = f[j] - a;
            float d2 = __shfl_xor_sync(0xffffffffu, d, 2);
            f[j] = s + d2;
        }
    }

    // ---- Stage i2: lane bits [3:2], 2-shuffle identity, fold 1/16 ----
    {
        float* f = reinterpret_cast<float*>(v);
        #pragma unroll
        for (int j = 0; j < 16; j++) {
            float a  = __shfl_xor_sync(0xffffffffu, f[j], 4);
            float s  = f[j] + a;
            float d  = f[j] - a;
            float d2 = __shfl_xor_sync(0xffffffffu, d, 8);
            f[j] = (s + d2) * 0.0625f;
        }
    }

    float4* op = reinterpret_cast<float4*>(out) + base4;
    #pragma unroll
    for (int c = 0; c < 4; c++)
        __stcs(op + 32 * c, v[c]);
}

extern "C" void kernel_launch(void* const* d_in, const int* in_sizes, int n_in,
                              void* d_out, int out_size)
{
    const float* x = (const float*)d_in[0];
    float* out = (float*)d_out;

    // out_size = 2*4096*8192 = 67,108,864 floats.
    // One warp handles 512 floats; 8 warps (256 threads) per CTA -> 4096 floats/CTA.
    const long long n = (long long)out_size;
    const int cta_elems = 4096;
    const int grid = (int)(n / cta_elems);   // 16384, exact

    hadamard256_kernel<<<grid, 256>>>(x, out);
}